// round 4
// baseline (speedup 1.0000x reference)
#include <cuda_runtime.h>
#include <cuda_fp16.h>
#include <cstdint>

#define DIM    4096
#define NITER  20
#define NBLK   148
#define NTHR   1024
#define CROWS  27                       // rows of Ê cached in smem (fp16)

// smem: CROWS rows of half (8KB each) + partials + v
#define P_STRIDE 33
#define SMEM_BYTES (CROWS * DIM * 2 + 28 * P_STRIDE * 4 + 28 * 4)

// Scratch (static __device__ arrays = allowed scratch)
__device__ float  g_Ef[(size_t)DIM * DIM];   // fp32 E scratch (setup only)
__device__ __half g_Eh[(size_t)DIM * DIM];   // fp16 scaled E (only uncached rows used)
__device__ float  g_usum[3][DIM];            // triple-buffered column sums
__device__ unsigned int g_bar;

// g = -log(-log(noise+eps)+eps); returns exp(logit + g)
__device__ __forceinline__ float gumbel_exp(float logit, float noise) {
    const float EPS = 1e-10f;
    float y = noise + EPS;
    float u = y - 1.0f;
    float w;
    if (fabsf(u) < 0.125f) {
        float p = 1.0f + u * (-0.5f + u * (0.33333333f + u * (-0.25f
                   + u * (0.2f + u * (-0.16666667f + u * 0.14285715f)))));
        w = -(u * p);
    } else {
        w = -__logf(y);
    }
    float g = -__logf(w + EPS);
    return __expf(logit + g);
}

__global__ void reset_kernel() { g_bar = 0u; }

__device__ __forceinline__ float warp_sum(float s) {
    #pragma unroll
    for (int o = 16; o; o >>= 1) s += __shfl_down_sync(0xffffffffu, s, o);
    return s;
}

__global__ __launch_bounds__(NTHR, 1)
void sinkhorn_kernel(const float* __restrict__ logits,
                     const float* __restrict__ noise,
                     float* __restrict__ out) {
    extern __shared__ unsigned char smraw[];
    __half* Eh_sm = reinterpret_cast<__half*>(smraw);                 // CROWS x DIM
    float*  p_sm  = reinterpret_cast<float*>(smraw + CROWS * DIM * 2); // 28 x 33
    float*  v_sm  = p_sm + 28 * P_STRIDE;                              // 28

    const int tid  = threadIdx.x;
    const int bid  = blockIdx.x;
    const int lane = tid & 31;
    const int wid  = tid >> 5;
    const int nr   = (DIM - bid + NBLK - 1) / NBLK;   // 28 (bid<100) else 27
    unsigned epoch = 0;

    auto gsync = [&]() {
        __syncthreads();
        __threadfence();
        ++epoch;
        if (tid == 0) {
            atomicAdd(&g_bar, 1u);
            const unsigned target = epoch * NBLK;
            while (*((volatile unsigned*)&g_bar) < target) { }
            __threadfence();
        }
        __syncthreads();
    };

    // helper: load this thread's 4 cols of local row k as float4
    auto load_row4 = [&](int k) -> float4 {
        uint2 raw;
        if (k < CROWS) {
            raw = reinterpret_cast<const uint2*>(Eh_sm + (size_t)k * DIM)[tid];
        } else {
            const int row = k * NBLK + bid;
            raw = reinterpret_cast<const uint2*>(g_Eh + (size_t)row * DIM)[tid];
        }
        __half2 h0 = *reinterpret_cast<__half2*>(&raw.x);
        __half2 h1 = *reinterpret_cast<__half2*>(&raw.y);
        float2 f0 = __half22float2(h0);
        float2 f1 = __half22float2(h1);
        return make_float4(f0.x, f0.y, f1.x, f1.y);
    };

    // ================= setup =================
    // pass A: E = exp(logits+gumbel) fp32 -> scratch; rowsum -> v1
    for (int k = 0; k < nr; ++k) {
        const int row = k * NBLK + bid;
        const float4 l = reinterpret_cast<const float4*>(logits + (size_t)row * DIM)[tid];
        const float4 n = reinterpret_cast<const float4*>(noise  + (size_t)row * DIM)[tid];
        float4 e;
        e.x = gumbel_exp(l.x, n.x);
        e.y = gumbel_exp(l.y, n.y);
        e.z = gumbel_exp(l.z, n.z);
        e.w = gumbel_exp(l.w, n.w);
        reinterpret_cast<float4*>(g_Ef + (size_t)row * DIM)[tid] = e;
        float p = warp_sum(e.x + e.y + e.z + e.w);
        if (lane == 0) p_sm[k * P_STRIDE + wid] = p;
    }
    // zero usum buffers 0 and 1 (slices)
    if (tid < 28) {
        int j = bid * 28 + tid;
        if (j < DIM) { g_usum[0][j] = 0.0f; g_usum[1][j] = 0.0f; }
    }
    __syncthreads();
    if (wid < nr) {
        float s = warp_sum(p_sm[wid * P_STRIDE + lane]);
        if (lane == 0) v_sm[wid] = 1.0f / s;    // v1
    }
    __syncthreads();
    // pass B: Ê = E * v1 -> fp16 (smem for cached rows, global for the rest)
    for (int k = 0; k < nr; ++k) {
        const int row = k * NBLK + bid;
        const float v1 = v_sm[k];
        float4 e = reinterpret_cast<const float4*>(g_Ef + (size_t)row * DIM)[tid];
        __half2 h0 = __floats2half2_rn(e.x * v1, e.y * v1);
        __half2 h1 = __floats2half2_rn(e.z * v1, e.w * v1);
        uint2 raw;
        raw.x = *reinterpret_cast<unsigned*>(&h0);
        raw.y = *reinterpret_cast<unsigned*>(&h1);
        if (k < CROWS)
            reinterpret_cast<uint2*>(Eh_sm + (size_t)k * DIM)[tid] = raw;
        else
            reinterpret_cast<uint2*>(g_Eh + (size_t)row * DIM)[tid] = raw;
    }
    gsync();   // barrier #1: usum[0], usum[1] zeroed everywhere

    // ============ first column pass: u = 1/colsum(Ê) -> usum[0] ============
    {
        float4 acc = make_float4(0.f, 0.f, 0.f, 0.f);
        for (int k = 0; k < nr; ++k) {
            float4 e = load_row4(k);
            acc.x += e.x; acc.y += e.y; acc.z += e.z; acc.w += e.w;
        }
        float* un = g_usum[0];
        atomicAdd(&un[4 * tid + 0], acc.x);
        atomicAdd(&un[4 * tid + 1], acc.y);
        atomicAdd(&un[4 * tid + 2], acc.z);
        atomicAdd(&un[4 * tid + 3], acc.w);
    }
    gsync();   // barrier #2

    // ============ 19 fused iterations ============
    for (int it = 0; it < NITER - 1; ++it) {
        const int rb = it % 3;              // read buffer
        const int wb = (it + 1) % 3;        // write buffer (pre-zeroed)
        const int zb = (it + 2) % 3;        // zero for iteration it+1

        // u into registers
        float4 us = reinterpret_cast<const float4*>(g_usum[rb])[tid];
        float4 u;
        u.x = 1.0f / us.x; u.y = 1.0f / us.y; u.z = 1.0f / us.z; u.w = 1.0f / us.w;

        // zero the stale buffer slice (last read 2 barriers ago)
        if (tid < 28) {
            int j = bid * 28 + tid;
            if (j < DIM) g_usum[zb][j] = 0.0f;
        }

        // ---- row pass: rowsum_k = sum_j Ê[k,j] * u_j ----
        for (int k = 0; k < nr; ++k) {
            float4 e = load_row4(k);
            float p = fmaf(e.x, u.x, fmaf(e.y, u.y, fmaf(e.z, u.z, e.w * u.w)));
            p = warp_sum(p);
            if (lane == 0) p_sm[k * P_STRIDE + wid] = p;
        }
        __syncthreads();
        if (wid < nr) {
            float s = warp_sum(p_sm[wid * P_STRIDE + lane]);
            if (lane == 0) v_sm[wid] = 1.0f / s;
        }
        __syncthreads();

        // ---- col pass: usum[wb][j] += sum_k Ê[k,j] * v_k ----
        float4 acc = make_float4(0.f, 0.f, 0.f, 0.f);
        for (int k = 0; k < nr; ++k) {
            float4 e = load_row4(k);
            const float vv = v_sm[k];
            acc.x = fmaf(e.x, vv, acc.x);
            acc.y = fmaf(e.y, vv, acc.y);
            acc.z = fmaf(e.z, vv, acc.z);
            acc.w = fmaf(e.w, vv, acc.w);
        }
        float* un = g_usum[wb];
        atomicAdd(&un[4 * tid + 0], acc.x);
        atomicAdd(&un[4 * tid + 1], acc.y);
        atomicAdd(&un[4 * tid + 2], acc.z);
        atomicAdd(&un[4 * tid + 3], acc.w);

        gsync();
    }

    // ============ final: out = Ê * v * u ============
    {
        const int rb = (NITER - 1) % 3;     // buffer written by last iteration
        float4 us = reinterpret_cast<const float4*>(g_usum[rb])[tid];
        float4 u;
        u.x = 1.0f / us.x; u.y = 1.0f / us.y; u.z = 1.0f / us.z; u.w = 1.0f / us.w;

        for (int k = 0; k < nr; ++k) {
            const int row = k * NBLK + bid;
            const float v = v_sm[k];        // v from the last fused iteration
            float4 e = load_row4(k);
            float4 o;
            o.x = e.x * v * u.x;
            o.y = e.y * v * u.y;
            o.z = e.z * v * u.z;
            o.w = e.w * v * u.w;
            reinterpret_cast<float4*>(out + (size_t)row * DIM)[tid] = o;
        }
    }
}

extern "C" void kernel_launch(void* const* d_in, const int* in_sizes, int n_in,
                              void* d_out, int out_size) {
    const float* logits = (const float*)d_in[0];
    const float* noise  = (const float*)d_in[1];
    float* out = (float*)d_out;

    static bool configured = false;
    if (!configured) {
        cudaFuncSetAttribute(sinkhorn_kernel,
                             cudaFuncAttributeMaxDynamicSharedMemorySize, SMEM_BYTES);
        configured = true;
    }

    reset_kernel<<<1, 1>>>();
    sinkhorn_kernel<<<NBLK, NTHR, SMEM_BYTES>>>(logits, noise, out);
}

// round 5
// speedup vs baseline: 1.0636x; 1.0636x over previous
#include <cuda_runtime.h>
#include <cuda_fp16.h>
#include <cstdint>

#define DIM    4096
#define NITER  20
#define NBLK   148
#define NTHR   1024
#define CROWS  26                       // rows of Ê cached in smem (fp16)

#define SMEM_BYTES (CROWS * DIM * 2 + DIM * 4 + 32 * 4)   // Ê rows + u_inv + v_sm

// Scratch (static __device__ arrays = allowed scratch)
__device__ __align__(16) float  g_Ef[(size_t)DIM * DIM];   // fp32 E scratch (setup only)
__device__ __align__(16) __half g_Eh[(size_t)DIM * DIM];   // fp16 scaled E (uncached rows)
__device__ __align__(16) float  g_usum[3][DIM];            // triple-buffered column sums
__device__ unsigned int g_bar;

// g = -log(-log(noise+eps)+eps); returns exp(logit + g)
__device__ __forceinline__ float gumbel_exp(float logit, float noise) {
    const float EPS = 1e-10f;
    float y = noise + EPS;
    float u = y - 1.0f;
    float w;
    if (fabsf(u) < 0.125f) {
        float p = 1.0f + u * (-0.5f + u * (0.33333333f + u * (-0.25f
                   + u * (0.2f + u * (-0.16666667f + u * 0.14285715f)))));
        w = -(u * p);
    } else {
        w = -__logf(y);
    }
    float g = -__logf(w + EPS);
    return __expf(logit + g);
}

__global__ void reset_kernel() {
    int i = blockIdx.x * blockDim.x + threadIdx.x;
    if (i == 0) g_bar = 0u;
    if (i < 3 * DIM) (&g_usum[0][0])[i] = 0.0f;
}

__device__ __forceinline__ float warp_sum(float s) {
    #pragma unroll
    for (int o = 16; o; o >>= 1) s += __shfl_down_sync(0xffffffffu, s, o);
    return s;
}

// uint4 (8 halves) -> two float4
__device__ __forceinline__ void cvt8(uint4 r, float4& a, float4& b) {
    float2 f0 = __half22float2(*reinterpret_cast<__half2*>(&r.x));
    float2 f1 = __half22float2(*reinterpret_cast<__half2*>(&r.y));
    float2 f2 = __half22float2(*reinterpret_cast<__half2*>(&r.z));
    float2 f3 = __half22float2(*reinterpret_cast<__half2*>(&r.w));
    a = make_float4(f0.x, f0.y, f1.x, f1.y);
    b = make_float4(f2.x, f2.y, f3.x, f3.y);
}

__device__ __forceinline__ float4 cvt4(uint2 r) {
    float2 f0 = __half22float2(*reinterpret_cast<__half2*>(&r.x));
    float2 f1 = __half22float2(*reinterpret_cast<__half2*>(&r.y));
    return make_float4(f0.x, f0.y, f1.x, f1.y);
}

__global__ __launch_bounds__(NTHR, 1)
void sinkhorn_kernel(const float* __restrict__ logits,
                     const float* __restrict__ noise,
                     float* __restrict__ out) {
    extern __shared__ __align__(16) unsigned char smraw[];
    __half* Eh_sm = reinterpret_cast<__half*>(smraw);                       // CROWS x DIM
    float*  u_inv = reinterpret_cast<float*>(smraw + CROWS * DIM * 2);      // DIM
    float*  v_sm  = u_inv + DIM;                                            // 28

    const int tid  = threadIdx.x;
    const int bid  = blockIdx.x;
    const int lane = tid & 31;
    const int wid  = tid >> 5;
    const int nr   = (DIM - bid + NBLK - 1) / NBLK;   // 28 (bid<100) else 27
    unsigned epoch = 0;

    auto gsync = [&]() {
        __syncthreads();
        __threadfence();
        ++epoch;
        if (tid == 0) {
            atomicAdd(&g_bar, 1u);
            const unsigned target = epoch * NBLK;
            while (*((volatile unsigned*)&g_bar) < target) { }
            __threadfence();
        }
        __syncthreads();
    };

    // local-row-k -> fp16 row pointer (smem for k<CROWS, global otherwise)
    auto rowptr = [&](int k) -> const __half* {
        return (k < CROWS) ? (Eh_sm + (size_t)k * DIM)
                           : (g_Eh + (size_t)(k * NBLK + bid) * DIM);
    };

    // ================= setup =================
    // pass A: warp-per-row, E=exp(logits+gumbel) fp32 -> g_Ef; rowsum -> v_sm
    if (wid < nr) {
        const int row = wid * NBLK + bid;
        const float* lrow = logits + (size_t)row * DIM;
        const float* nrow = noise  + (size_t)row * DIM;
        float* erow = g_Ef + (size_t)row * DIM;
        float s = 0.0f;
        #pragma unroll 4
        for (int j = lane; j < DIM; j += 32) {
            float e = gumbel_exp(lrow[j], nrow[j]);
            erow[j] = e;
            s += e;
        }
        s = warp_sum(s);
        if (lane == 0) v_sm[wid] = 1.0f / s;
    }
    __syncthreads();

    // pass B: thread-per-4cols: scale by 1/rowsum, store fp16, fuse first col pass
    {
        float4 acc = make_float4(0.f, 0.f, 0.f, 0.f);
        for (int k = 0; k < nr; ++k) {
            const int row = k * NBLK + bid;
            const float v1 = v_sm[k];
            float4 e = reinterpret_cast<const float4*>(g_Ef + (size_t)row * DIM)[tid];
            e.x *= v1; e.y *= v1; e.z *= v1; e.w *= v1;
            __half2 h0 = __floats2half2_rn(e.x, e.y);
            __half2 h1 = __floats2half2_rn(e.z, e.w);
            uint2 raw;
            raw.x = *reinterpret_cast<unsigned*>(&h0);
            raw.y = *reinterpret_cast<unsigned*>(&h1);
            if (k < CROWS)
                reinterpret_cast<uint2*>(Eh_sm + (size_t)k * DIM)[tid] = raw;
            else
                reinterpret_cast<uint2*>(g_Eh + (size_t)row * DIM)[tid] = raw;
            // accumulate the quantized values so colsums match stored Ê exactly
            float4 q = cvt4(raw);
            acc.x += q.x; acc.y += q.y; acc.z += q.z; acc.w += q.w;
        }
        float* u0 = g_usum[0];     // pre-zeroed by reset_kernel
        atomicAdd(&u0[4 * tid + 0], acc.x);
        atomicAdd(&u0[4 * tid + 1], acc.y);
        atomicAdd(&u0[4 * tid + 2], acc.z);
        atomicAdd(&u0[4 * tid + 3], acc.w);
    }
    gsync();

    // ============ 19 fused iterations ============
    for (int it = 0; it < NITER - 1; ++it) {
        const int rb = it % 3;
        const int wb = (it + 1) % 3;    // pre-zeroed
        const int zb = (it + 2) % 3;    // zero now for next iteration

        // u_inv into smem
        {
            float4 us = reinterpret_cast<const float4*>(g_usum[rb])[tid];
            float4 u = make_float4(1.0f / us.x, 1.0f / us.y, 1.0f / us.z, 1.0f / us.w);
            reinterpret_cast<float4*>(u_inv)[tid] = u;
        }
        // zero stale buffer (last read before previous gsync)
        if (tid < 28) {
            int j = bid * 28 + tid;
            if (j < DIM) g_usum[zb][j] = 0.0f;
        }
        __syncthreads();

        // ---- row pass: warp-per-row-pair, u loads shared between the two rows ----
        if (wid < 14) {
            const int r0 = 2 * wid, r1 = 2 * wid + 1;
            const bool has1 = (r1 < nr);
            const uint4* e0 = reinterpret_cast<const uint4*>(rowptr(r0));
            const uint4* e1 = reinterpret_cast<const uint4*>(rowptr(has1 ? r1 : r0));
            const float4* u4 = reinterpret_cast<const float4*>(u_inv);
            float s0 = 0.f, s1 = 0.f;
            #pragma unroll 4
            for (int c = 0; c < 16; ++c) {
                const int idx = c * 32 + lane;
                uint4 ra = e0[idx];
                uint4 rbv = e1[idx];
                float4 ua = u4[2 * idx];
                float4 ub = u4[2 * idx + 1];
                float4 a0, b0, a1, b1;
                cvt8(ra, a0, b0);
                cvt8(rbv, a1, b1);
                s0 = fmaf(a0.x, ua.x, s0); s0 = fmaf(a0.y, ua.y, s0);
                s0 = fmaf(a0.z, ua.z, s0); s0 = fmaf(a0.w, ua.w, s0);
                s0 = fmaf(b0.x, ub.x, s0); s0 = fmaf(b0.y, ub.y, s0);
                s0 = fmaf(b0.z, ub.z, s0); s0 = fmaf(b0.w, ub.w, s0);
                s1 = fmaf(a1.x, ua.x, s1); s1 = fmaf(a1.y, ua.y, s1);
                s1 = fmaf(a1.z, ua.z, s1); s1 = fmaf(a1.w, ua.w, s1);
                s1 = fmaf(b1.x, ub.x, s1); s1 = fmaf(b1.y, ub.y, s1);
                s1 = fmaf(b1.z, ub.z, s1); s1 = fmaf(b1.w, ub.w, s1);
            }
            s0 = warp_sum(s0);
            s1 = warp_sum(s1);
            if (lane == 0) {
                v_sm[r0] = 1.0f / s0;
                if (has1) v_sm[r1] = 1.0f / s1;
            }
        }
        __syncthreads();

        // ---- col pass: thread-per-4cols, usum[wb] += sum_k Ê[k,:] * v_k ----
        {
            float4 acc = make_float4(0.f, 0.f, 0.f, 0.f);
            #pragma unroll 13
            for (int k = 0; k < CROWS; ++k) {
                float4 e = cvt4(reinterpret_cast<const uint2*>(Eh_sm + (size_t)k * DIM)[tid]);
                const float vv = v_sm[k];
                acc.x = fmaf(e.x, vv, acc.x);
                acc.y = fmaf(e.y, vv, acc.y);
                acc.z = fmaf(e.z, vv, acc.z);
                acc.w = fmaf(e.w, vv, acc.w);
            }
            for (int k = CROWS; k < nr; ++k) {
                float4 e = cvt4(reinterpret_cast<const uint2*>(g_Eh + (size_t)(k * NBLK + bid) * DIM)[tid]);
                const float vv = v_sm[k];
                acc.x = fmaf(e.x, vv, acc.x);
                acc.y = fmaf(e.y, vv, acc.y);
                acc.z = fmaf(e.z, vv, acc.z);
                acc.w = fmaf(e.w, vv, acc.w);
            }
            float* un = g_usum[wb];
            atomicAdd(&un[4 * tid + 0], acc.x);
            atomicAdd(&un[4 * tid + 1], acc.y);
            atomicAdd(&un[4 * tid + 2], acc.z);
            atomicAdd(&un[4 * tid + 3], acc.w);
        }
        gsync();
    }

    // ============ final: out = Ê * v * u ============
    {
        float4 us = reinterpret_cast<const float4*>(g_usum[(NITER - 1) % 3])[tid];
        float4 u = make_float4(1.0f / us.x, 1.0f / us.y, 1.0f / us.z, 1.0f / us.w);
        for (int k = 0; k < nr; ++k) {
            const int row = k * NBLK + bid;
            const float v = v_sm[k];
            float4 e = cvt4((k < CROWS)
                ? reinterpret_cast<const uint2*>(Eh_sm + (size_t)k * DIM)[tid]
                : reinterpret_cast<const uint2*>(g_Eh + (size_t)row * DIM)[tid]);
            float4 o;
            o.x = e.x * v * u.x;
            o.y = e.y * v * u.y;
            o.z = e.z * v * u.z;
            o.w = e.w * v * u.w;
            reinterpret_cast<float4*>(out + (size_t)row * DIM)[tid] = o;
        }
    }
}

extern "C" void kernel_launch(void* const* d_in, const int* in_sizes, int n_in,
                              void* d_out, int out_size) {
    const float* logits = (const float*)d_in[0];
    const float* noise  = (const float*)d_in[1];
    float* out = (float*)d_out;

    static bool configured = false;
    if (!configured) {
        cudaFuncSetAttribute(sinkhorn_kernel,
                             cudaFuncAttributeMaxDynamicSharedMemorySize, SMEM_BYTES);
        configured = true;
    }

    reset_kernel<<<16, 1024>>>();
    sinkhorn_kernel<<<NBLK, NTHR, SMEM_BYTES>>>(logits, noise, out);
}

// round 6
// speedup vs baseline: 1.6540x; 1.5551x over previous
#include <cuda_runtime.h>
#include <cuda_fp16.h>
#include <cstdint>

#define DIM   4096
#define NITER 20
#define NBLK  148
#define NTHR  1024
#define NREP  4

// Scratch (static __device__ arrays = allowed scratch)
__device__ __align__(16) __half g_Eh[(size_t)DIM * DIM];      // fp16 row-scaled E
__device__ __align__(16) float  g_usum[3][NREP][DIM];         // phase x replica colsums
__device__ unsigned int g_bar;

// g = -log(-log(noise+eps)+eps); returns exp(logit + g)
__device__ __forceinline__ float gumbel_exp(float logit, float noise) {
    const float EPS = 1e-10f;
    float y = noise + EPS;
    float u = y - 1.0f;
    float w;
    if (fabsf(u) < 0.125f) {
        float p = 1.0f + u * (-0.5f + u * (0.33333333f + u * (-0.25f
                   + u * (0.2f + u * (-0.16666667f + u * 0.14285715f)))));
        w = -(u * p);
    } else {
        w = -__logf(y);
    }
    float g = -__logf(w + EPS);
    return __expf(logit + g);
}

__global__ void reset_kernel() {
    int i = blockIdx.x * blockDim.x + threadIdx.x;
    if (i == 0) g_bar = 0u;
    if (i < 3 * NREP * DIM) ((float*)g_usum)[i] = 0.0f;
}

__device__ __forceinline__ float warp_sum(float s) {
    #pragma unroll
    for (int o = 16; o; o >>= 1) s += __shfl_down_sync(0xffffffffu, s, o);
    return s;
}

// fence-free grid barrier primitives (no CCTL.IVALL -> L1D survives)
__device__ __forceinline__ void bar_arrive_release() {
    asm volatile("red.release.gpu.global.add.u32 [%0], 1;" :: "l"(&g_bar) : "memory");
}
__device__ __forceinline__ unsigned bar_poll_acquire() {
    unsigned v;
    asm volatile("ld.acquire.gpu.global.u32 %0, [%1];" : "=r"(v) : "l"(&g_bar) : "memory");
    return v;
}

__device__ __forceinline__ float4 cvt4(uint2 r) {
    float2 f0 = __half22float2(*reinterpret_cast<__half2*>(&r.x));
    float2 f1 = __half22float2(*reinterpret_cast<__half2*>(&r.y));
    return make_float4(f0.x, f0.y, f1.x, f1.y);
}

__global__ __launch_bounds__(NTHR, 1)
void sinkhorn_kernel(const float* __restrict__ logits,
                     const float* __restrict__ noise,
                     float* __restrict__ out) {
    __shared__ __align__(16) __half u_h[DIM];   // 8 KB fp16 inverted colsums
    __shared__ float v_sm[32];

    const int tid  = threadIdx.x;
    const int bid  = blockIdx.x;
    const int lane = tid & 31;
    const int wid  = tid >> 5;
    const int nr   = (DIM - bid + NBLK - 1) / NBLK;   // 28 (bid<100) else 27
    const int rep  = bid & (NREP - 1);
    unsigned epoch = 0;

    auto gsync = [&]() {
        __syncthreads();
        ++epoch;
        if (tid == 0) {
            bar_arrive_release();
            const unsigned target = epoch * NBLK;
            while (bar_poll_acquire() < target) { }
        }
        __syncthreads();
    };

    // ================= setup =================
    // warp-per-row: e=exp(logit+gumbel) staged fp32 in `out` (block-private rows,
    // overwritten by final), rowsum -> scale -> fp16 g_Eh
    if (wid < nr) {
        const int row = wid * NBLK + bid;
        const float4* l4 = reinterpret_cast<const float4*>(logits + (size_t)row * DIM);
        const float4* n4 = reinterpret_cast<const float4*>(noise  + (size_t)row * DIM);
        float4*       s4 = reinterpret_cast<float4*>(out + (size_t)row * DIM);
        float s = 0.0f;
        #pragma unroll 4
        for (int c = lane; c < DIM / 4; c += 32) {
            float4 l = l4[c], n = n4[c], e;
            e.x = gumbel_exp(l.x, n.x);
            e.y = gumbel_exp(l.y, n.y);
            e.z = gumbel_exp(l.z, n.z);
            e.w = gumbel_exp(l.w, n.w);
            s4[c] = e;
            s += (e.x + e.y) + (e.z + e.w);
        }
        s = warp_sum(s);
        const float vin = __shfl_sync(0xffffffffu, __frcp_rn(s), 0);
        uint2* eh = reinterpret_cast<uint2*>(g_Eh + (size_t)row * DIM);
        #pragma unroll 4
        for (int c = lane; c < DIM / 4; c += 32) {
            float4 e = s4[c];                       // L1-hot readback
            __half2 h0 = __floats2half2_rn(e.x * vin, e.y * vin);
            __half2 h1 = __floats2half2_rn(e.z * vin, e.w * vin);
            uint2 r;
            r.x = *reinterpret_cast<unsigned*>(&h0);
            r.y = *reinterpret_cast<unsigned*>(&h1);
            eh[c] = r;
        }
    }
    __syncthreads();

    // initial col pass: usum[0] += colsum(Ê)  (thread-per-4cols, replica atomics)
    {
        float4 acc = make_float4(0.f, 0.f, 0.f, 0.f);
        #pragma unroll 4
        for (int k = 0; k < nr; ++k) {
            float4 e = cvt4(reinterpret_cast<const uint2*>(g_Eh + (size_t)(k * NBLK + bid) * DIM)[tid]);
            acc.x += e.x; acc.y += e.y; acc.z += e.z; acc.w += e.w;
        }
        float* dst = g_usum[0][rep];
        atomicAdd(&dst[4 * tid + 0], acc.x);
        atomicAdd(&dst[4 * tid + 1], acc.y);
        atomicAdd(&dst[4 * tid + 2], acc.z);
        atomicAdd(&dst[4 * tid + 3], acc.w);
    }
    gsync();

    // ================ 19 fused iterations ================
    for (int it = 0; it < NITER - 1; ++it) {
        const int rb = it % 3;
        const int wb = (it + 1) % 3;   // pre-zeroed
        const int zb = (it + 2) % 3;   // zero now for use next iteration

        // u_h = fp16(1 / sum of replicas)   (L2 reads, bypass L1)
        {
            float4 a = __ldcg(reinterpret_cast<const float4*>(g_usum[rb][0]) + tid);
            float4 b = __ldcg(reinterpret_cast<const float4*>(g_usum[rb][1]) + tid);
            float4 c = __ldcg(reinterpret_cast<const float4*>(g_usum[rb][2]) + tid);
            float4 d = __ldcg(reinterpret_cast<const float4*>(g_usum[rb][3]) + tid);
            float sx = (a.x + b.x) + (c.x + d.x);
            float sy = (a.y + b.y) + (c.y + d.y);
            float sz = (a.z + b.z) + (c.z + d.z);
            float sw = (a.w + b.w) + (c.w + d.w);
            __half2 h0 = __floats2half2_rn(__frcp_rn(sx), __frcp_rn(sy));
            __half2 h1 = __floats2half2_rn(__frcp_rn(sz), __frcp_rn(sw));
            uint2 r;
            r.x = *reinterpret_cast<unsigned*>(&h0);
            r.y = *reinterpret_cast<unsigned*>(&h1);
            reinterpret_cast<uint2*>(u_h)[tid] = r;
        }
        // zero stale replica buffer (plain stores; consumed two barriers later)
        if (tid < 111) {
            int i = bid * 111 + tid;
            if (i < NREP * DIM) ((float*)g_usum[zb])[i] = 0.0f;
        }
        __syncthreads();

        // ---- row pass: warp-per-row, fp16 products, fp32 accumulate ----
        if (wid < nr) {
            const uint4* e4 = reinterpret_cast<const uint4*>(g_Eh + (size_t)(wid * NBLK + bid) * DIM);
            const uint4* u4 = reinterpret_cast<const uint4*>(u_h);
            float s = 0.0f;
            #pragma unroll 4
            for (int c = 0; c < 16; ++c) {
                const int idx = c * 32 + lane;
                uint4 e = e4[idx];
                uint4 u = u4[idx];
                __half2 p0 = __hmul2(*reinterpret_cast<__half2*>(&e.x), *reinterpret_cast<__half2*>(&u.x));
                __half2 p1 = __hmul2(*reinterpret_cast<__half2*>(&e.y), *reinterpret_cast<__half2*>(&u.y));
                __half2 p2 = __hmul2(*reinterpret_cast<__half2*>(&e.z), *reinterpret_cast<__half2*>(&u.z));
                __half2 p3 = __hmul2(*reinterpret_cast<__half2*>(&e.w), *reinterpret_cast<__half2*>(&u.w));
                float2 f0 = __half22float2(p0);
                float2 f1 = __half22float2(p1);
                float2 f2 = __half22float2(p2);
                float2 f3 = __half22float2(p3);
                s += ((f0.x + f0.y) + (f1.x + f1.y)) + ((f2.x + f2.y) + (f3.x + f3.y));
            }
            s = warp_sum(s);
            if (lane == 0) v_sm[wid] = __frcp_rn(s);
        }
        __syncthreads();

        // ---- col pass: thread-per-4cols over own rows (L1-hot) ----
        {
            float4 acc = make_float4(0.f, 0.f, 0.f, 0.f);
            #pragma unroll 4
            for (int k = 0; k < nr; ++k) {
                float4 e = cvt4(reinterpret_cast<const uint2*>(g_Eh + (size_t)(k * NBLK + bid) * DIM)[tid]);
                const float vv = v_sm[k];
                acc.x = fmaf(e.x, vv, acc.x);
                acc.y = fmaf(e.y, vv, acc.y);
                acc.z = fmaf(e.z, vv, acc.z);
                acc.w = fmaf(e.w, vv, acc.w);
            }
            float* dst = g_usum[wb][rep];
            atomicAdd(&dst[4 * tid + 0], acc.x);
            atomicAdd(&dst[4 * tid + 1], acc.y);
            atomicAdd(&dst[4 * tid + 2], acc.z);
            atomicAdd(&dst[4 * tid + 3], acc.w);
        }
        gsync();
    }

    // ================ final: out = Ê * v * u  (u in fp32) ================
    {
        const int fb = (NITER - 1) % 3;
        float4 a = __ldcg(reinterpret_cast<const float4*>(g_usum[fb][0]) + tid);
        float4 b = __ldcg(reinterpret_cast<const float4*>(g_usum[fb][1]) + tid);
        float4 c = __ldcg(reinterpret_cast<const float4*>(g_usum[fb][2]) + tid);
        float4 d = __ldcg(reinterpret_cast<const float4*>(g_usum[fb][3]) + tid);
        const float ux = __frcp_rn((a.x + b.x) + (c.x + d.x));
        const float uy = __frcp_rn((a.y + b.y) + (c.y + d.y));
        const float uz = __frcp_rn((a.z + b.z) + (c.z + d.z));
        const float uw = __frcp_rn((a.w + b.w) + (c.w + d.w));
        #pragma unroll 4
        for (int k = 0; k < nr; ++k) {
            const int row = k * NBLK + bid;
            float4 e = cvt4(reinterpret_cast<const uint2*>(g_Eh + (size_t)row * DIM)[tid]);
            const float vv = v_sm[k];
            float4 o;
            o.x = e.x * vv * ux;
            o.y = e.y * vv * uy;
            o.z = e.z * vv * uz;
            o.w = e.w * vv * uw;
            reinterpret_cast<float4*>(out + (size_t)row * DIM)[tid] = o;
        }
    }
}

extern "C" void kernel_launch(void* const* d_in, const int* in_sizes, int n_in,
                              void* d_out, int out_size) {
    const float* logits = (const float*)d_in[0];
    const float* noise  = (const float*)d_in[1];
    float* out = (float*)d_out;

    reset_kernel<<<48, 1024>>>();
    sinkhorn_kernel<<<NBLK, NTHR>>>(logits, noise, out);
}

// round 7
// speedup vs baseline: 1.7274x; 1.0444x over previous
#include <cuda_runtime.h>
#include <cuda_fp16.h>
#include <cstdint>

#define DIM   4096
#define NITER 20
#define NBLK  148
#define NTHR  1024
#define NREP  4

// Scratch (static __device__ arrays = allowed scratch)
__device__ __align__(16) __half g_Eh[(size_t)DIM * DIM];      // fp16 row-scaled E
__device__ __align__(16) float  g_usum[3][NREP][DIM];         // phase x replica colsums
__device__ unsigned int g_bar;

__global__ void reset_kernel() {
    int i = blockIdx.x * blockDim.x + threadIdx.x;
    if (i == 0) g_bar = 0u;
    if (i < 3 * NREP * DIM) ((float*)g_usum)[i] = 0.0f;
}

__device__ __forceinline__ float warp_sum(float s) {
    #pragma unroll
    for (int o = 16; o; o >>= 1) s += __shfl_down_sync(0xffffffffu, s, o);
    return s;
}

// fence-free grid barrier (no CCTL.IVALL -> L1D survives the whole kernel)
__device__ __forceinline__ void bar_arrive_release() {
    asm volatile("red.release.gpu.global.add.u32 [%0], 1;" :: "l"(&g_bar) : "memory");
}
__device__ __forceinline__ unsigned bar_poll_acquire() {
    unsigned v;
    asm volatile("ld.acquire.gpu.global.u32 %0, [%1];" : "=r"(v) : "l"(&g_bar) : "memory");
    return v;
}

__device__ __forceinline__ __half2 h2(unsigned r) { return *reinterpret_cast<__half2*>(&r); }

__device__ __forceinline__ float4 cvt4(uint2 r) {
    float2 f0 = __half22float2(h2(r.x));
    float2 f1 = __half22float2(h2(r.y));
    return make_float4(f0.x, f0.y, f1.x, f1.y);
}

// g = -log(-log(noise+eps)+eps); returns exp(logit + g)
__device__ __forceinline__ float gumbel_exp(float logit, float noise) {
    const float EPS = 1e-10f;
    float y = noise + EPS;
    float u = y - 1.0f;
    float w;
    if (fabsf(u) < 0.125f) {
        float p = 1.0f + u * (-0.5f + u * (0.33333333f + u * (-0.25f
                   + u * (0.2f + u * (-0.16666667f + u * 0.14285715f)))));
        w = -(u * p);
    } else {
        w = -__logf(y);
    }
    float g = -__logf(w + EPS);
    return __expf(logit + g);
}

__global__ __launch_bounds__(NTHR, 1)
void sinkhorn_kernel(const float* __restrict__ logits,
                     const float* __restrict__ noise,
                     float* __restrict__ out) {
    __shared__ __align__(16) __half u_h[DIM];   // 8 KB fp16 inverted colsums
    __shared__ float v_sm[32];
    __shared__ float p_sm[32];
    __shared__ float v_bc;

    const int tid  = threadIdx.x;
    const int bid  = blockIdx.x;
    const int lane = tid & 31;
    const int wid  = tid >> 5;
    const int nr   = (DIM - bid + NBLK - 1) / NBLK;   // 28 (bid<100) else 27
    const int rep  = bid & (NREP - 1);
    unsigned epoch = 0;

    auto gsync = [&]() {
        __syncthreads();
        ++epoch;
        if (tid == 0) {
            bar_arrive_release();
            const unsigned target = epoch * NBLK;
            while (bar_poll_acquire() < target) { }
        }
        __syncthreads();
    };

    // ================= setup: block-cooperative per row, zero staging =================
    // Row k: thread tid computes cols 4tid..4tid+3 (registers), block-reduces the
    // rowsum, scales -> fp16 -> g_Eh, and accumulates the initial column sums.
    {
        float4 acc = make_float4(0.f, 0.f, 0.f, 0.f);
        float4 l = reinterpret_cast<const float4*>(logits + (size_t)bid * DIM)[tid];
        float4 n = reinterpret_cast<const float4*>(noise  + (size_t)bid * DIM)[tid];
        for (int k = 0; k < nr; ++k) {
            float4 e;
            e.x = gumbel_exp(l.x, n.x);
            e.y = gumbel_exp(l.y, n.y);
            e.z = gumbel_exp(l.z, n.z);
            e.w = gumbel_exp(l.w, n.w);
            // prefetch next row (overlaps DRAM latency with the reduction below)
            if (k + 1 < nr) {
                const int nrow = (k + 1) * NBLK + bid;
                l = reinterpret_cast<const float4*>(logits + (size_t)nrow * DIM)[tid];
                n = reinterpret_cast<const float4*>(noise  + (size_t)nrow * DIM)[tid];
            }
            float s = warp_sum((e.x + e.y) + (e.z + e.w));
            if (lane == 0) p_sm[wid] = s;
            __syncthreads();
            if (wid == 0) {
                float t = warp_sum(p_sm[lane]);
                if (lane == 0) v_bc = __frcp_rn(t);
            }
            __syncthreads();
            const float vin = v_bc;
            __half2 h0 = __floats2half2_rn(e.x * vin, e.y * vin);
            __half2 h1 = __floats2half2_rn(e.z * vin, e.w * vin);
            uint2 r;
            r.x = *reinterpret_cast<unsigned*>(&h0);
            r.y = *reinterpret_cast<unsigned*>(&h1);
            reinterpret_cast<uint2*>(g_Eh + (size_t)(k * NBLK + bid) * DIM)[tid] = r;
            // accumulate the quantized values so colsums match stored Ê exactly
            float4 q = cvt4(r);
            acc.x += q.x; acc.y += q.y; acc.z += q.z; acc.w += q.w;
        }
        float* dst = g_usum[0][rep];
        atomicAdd(&dst[4 * tid + 0], acc.x);
        atomicAdd(&dst[4 * tid + 1], acc.y);
        atomicAdd(&dst[4 * tid + 2], acc.z);
        atomicAdd(&dst[4 * tid + 3], acc.w);
    }
    gsync();

    // ================ 19 fused iterations ================
    for (int it = 0; it < NITER - 1; ++it) {
        const int rb = it % 3;
        const int wb = (it + 1) % 3;   // pre-zeroed
        const int zb = (it + 2) % 3;   // zero now for use next iteration

        // u_h = fp16(1 / sum of replicas)   (L2 reads, bypass L1)
        {
            float4 a = __ldcg(reinterpret_cast<const float4*>(g_usum[rb][0]) + tid);
            float4 b = __ldcg(reinterpret_cast<const float4*>(g_usum[rb][1]) + tid);
            float4 c = __ldcg(reinterpret_cast<const float4*>(g_usum[rb][2]) + tid);
            float4 d = __ldcg(reinterpret_cast<const float4*>(g_usum[rb][3]) + tid);
            float sx = (a.x + b.x) + (c.x + d.x);
            float sy = (a.y + b.y) + (c.y + d.y);
            float sz = (a.z + b.z) + (c.z + d.z);
            float sw = (a.w + b.w) + (c.w + d.w);
            __half2 h0 = __floats2half2_rn(__frcp_rn(sx), __frcp_rn(sy));
            __half2 h1 = __floats2half2_rn(__frcp_rn(sz), __frcp_rn(sw));
            uint2 r;
            r.x = *reinterpret_cast<unsigned*>(&h0);
            r.y = *reinterpret_cast<unsigned*>(&h1);
            reinterpret_cast<uint2*>(u_h)[tid] = r;
        }
        // zero stale replica buffer (plain stores; consumed two barriers later)
        if (tid < 111) {
            int i = bid * 111 + tid;
            if (i < NREP * DIM) ((float*)g_usum[zb])[i] = 0.0f;
        }
        __syncthreads();

        // ---- row pass: warp per ROW PAIR; one u load serves two rows ----
        if (wid < 14) {
            const int r0 = 2 * wid, r1 = r0 + 1;
            const bool has1 = (r1 < nr);
            const uint4* e0 = reinterpret_cast<const uint4*>(g_Eh + (size_t)(r0 * NBLK + bid) * DIM);
            const uint4* e1 = reinterpret_cast<const uint4*>(g_Eh + (size_t)((has1 ? r1 : r0) * NBLK + bid) * DIM);
            const uint4* u4 = reinterpret_cast<const uint4*>(u_h);
            float s0a = 0.f, s0b = 0.f, s1a = 0.f, s1b = 0.f;
            #pragma unroll 4
            for (int c = 0; c < 16; ++c) {
                const int idx = c * 32 + lane;
                uint4 u = u4[idx];
                uint4 a = e0[idx];
                uint4 b = e1[idx];
                // row 0: hmul pairs, hadd2 pre-reduce, convert, fp32 accumulate
                __half2 q0 = __hadd2(__hmul2(h2(a.x), h2(u.x)), __hmul2(h2(a.y), h2(u.y)));
                __half2 q1 = __hadd2(__hmul2(h2(a.z), h2(u.z)), __hmul2(h2(a.w), h2(u.w)));
                float2 f0 = __half22float2(q0);
                float2 f1 = __half22float2(q1);
                s0a += f0.x + f0.y;
                s0b += f1.x + f1.y;
                // row 1
                __half2 q2 = __hadd2(__hmul2(h2(b.x), h2(u.x)), __hmul2(h2(b.y), h2(u.y)));
                __half2 q3 = __hadd2(__hmul2(h2(b.z), h2(u.z)), __hmul2(h2(b.w), h2(u.w)));
                float2 f2 = __half22float2(q2);
                float2 f3 = __half22float2(q3);
                s1a += f2.x + f2.y;
                s1b += f3.x + f3.y;
            }
            float s0 = warp_sum(s0a + s0b);
            float s1 = warp_sum(s1a + s1b);
            if (lane == 0) {
                v_sm[r0] = __frcp_rn(s0);
                if (has1) v_sm[r1] = __frcp_rn(s1);
            }
        }
        __syncthreads();

        // ---- col pass: thread-per-4cols over own rows (L1-hot) ----
        {
            float4 acc = make_float4(0.f, 0.f, 0.f, 0.f);
            #pragma unroll 4
            for (int k = 0; k < nr; ++k) {
                float4 e = cvt4(reinterpret_cast<const uint2*>(g_Eh + (size_t)(k * NBLK + bid) * DIM)[tid]);
                const float vv = v_sm[k];
                acc.x = fmaf(e.x, vv, acc.x);
                acc.y = fmaf(e.y, vv, acc.y);
                acc.z = fmaf(e.z, vv, acc.z);
                acc.w = fmaf(e.w, vv, acc.w);
            }
            float* dst = g_usum[wb][rep];
            atomicAdd(&dst[4 * tid + 0], acc.x);
            atomicAdd(&dst[4 * tid + 1], acc.y);
            atomicAdd(&dst[4 * tid + 2], acc.z);
            atomicAdd(&dst[4 * tid + 3], acc.w);
        }
        gsync();
    }

    // ================ final: out = Ê * v * u  (u in fp32) ================
    {
        const int fb = (NITER - 1) % 3;
        float4 a = __ldcg(reinterpret_cast<const float4*>(g_usum[fb][0]) + tid);
        float4 b = __ldcg(reinterpret_cast<const float4*>(g_usum[fb][1]) + tid);
        float4 c = __ldcg(reinterpret_cast<const float4*>(g_usum[fb][2]) + tid);
        float4 d = __ldcg(reinterpret_cast<const float4*>(g_usum[fb][3]) + tid);
        const float ux = __frcp_rn((a.x + b.x) + (c.x + d.x));
        const float uy = __frcp_rn((a.y + b.y) + (c.y + d.y));
        const float uz = __frcp_rn((a.z + b.z) + (c.z + d.z));
        const float uw = __frcp_rn((a.w + b.w) + (c.w + d.w));
        #pragma unroll 4
        for (int k = 0; k < nr; ++k) {
            const int row = k * NBLK + bid;
            float4 e = cvt4(reinterpret_cast<const uint2*>(g_Eh + (size_t)row * DIM)[tid]);
            const float vv = v_sm[k];
            float4 o;
            o.x = e.x * vv * ux;
            o.y = e.y * vv * uy;
            o.z = e.z * vv * uz;
            o.w = e.w * vv * uw;
            reinterpret_cast<float4*>(out + (size_t)row * DIM)[tid] = o;
        }
    }
}

extern "C" void kernel_launch(void* const* d_in, const int* in_sizes, int n_in,
                              void* d_out, int out_size) {
    const float* logits = (const float*)d_in[0];
    const float* noise  = (const float*)d_in[1];
    float* out = (float*)d_out;

    reset_kernel<<<48, 1024>>>();
    sinkhorn_kernel<<<NBLK, NTHR>>>(logits, noise, out);
}

// round 9
// speedup vs baseline: 1.8035x; 1.0441x over previous
#include <cuda_runtime.h>
#include <cuda_fp16.h>
#include <cstdint>

#define DIM   4096
#define NITER 20
#define NBLK  148
#define NTHR  1024
#define NREP  4
#define CROWS 13     // rows kept in smem; remaining rows live in L1

// Eh_sm + u_h + v_sm(32f) + p_sm(32f) + v_bc(1f) + pad
#define SMEM_BYTES (CROWS * DIM * 2 + DIM * 2 + 512)

// Scratch (static __device__ arrays = allowed scratch)
__device__ __align__(16) __half g_Eh[(size_t)DIM * DIM];      // fp16 row-scaled E (L1-resident rows)
__device__ __align__(16) float  g_usum[3][NREP][DIM];         // phase x replica colsums
__device__ unsigned int g_bar;

__global__ void reset_kernel() {
    int i = blockIdx.x * blockDim.x + threadIdx.x;
    if (i == 0) g_bar = 0u;
    if (i < 3 * NREP * DIM) ((float*)g_usum)[i] = 0.0f;
}

__device__ __forceinline__ float warp_sum(float s) {
    #pragma unroll
    for (int o = 16; o; o >>= 1) s += __shfl_down_sync(0xffffffffu, s, o);
    return s;
}

// fence-free grid barrier (no CCTL.IVALL -> L1D survives the whole kernel)
__device__ __forceinline__ void bar_arrive_release() {
    asm volatile("red.release.gpu.global.add.u32 [%0], 1;" :: "l"(&g_bar) : "memory");
}
__device__ __forceinline__ unsigned bar_poll_acquire() {
    unsigned v;
    asm volatile("ld.acquire.gpu.global.u32 %0, [%1];" : "=r"(v) : "l"(&g_bar) : "memory");
    return v;
}

__device__ __forceinline__ __half2 h2(unsigned r) { return *reinterpret_cast<__half2*>(&r); }

__device__ __forceinline__ float4 cvt4(uint2 r) {
    float2 f0 = __half22float2(h2(r.x));
    float2 f1 = __half22float2(h2(r.y));
    return make_float4(f0.x, f0.y, f1.x, f1.y);
}

// g = -log(-log(noise+eps)+eps); returns exp(logit + g)
__device__ __forceinline__ float gumbel_exp(float logit, float noise) {
    const float EPS = 1e-10f;
    float y = noise + EPS;
    float u = y - 1.0f;
    float w;
    if (fabsf(u) < 0.125f) {
        float p = 1.0f + u * (-0.5f + u * (0.33333333f + u * (-0.25f
                   + u * (0.2f + u * (-0.16666667f + u * 0.14285715f)))));
        w = -(u * p);
    } else {
        w = -__logf(y);
    }
    float g = -__logf(w + EPS);
    return __expf(logit + g);
}

// dot of two rows against u (fp16 mul, fp16 pair-add, fp32 accumulate)
__device__ __forceinline__ void dot2(const uint4* __restrict__ e0,
                                     const uint4* __restrict__ e1,
                                     const uint4* __restrict__ u4,
                                     int lane, float& s0, float& s1) {
    float s0a = 0.f, s0b = 0.f, s1a = 0.f, s1b = 0.f;
    #pragma unroll 4
    for (int c = 0; c < 16; ++c) {
        const int idx = c * 32 + lane;
        uint4 u = u4[idx];
        uint4 a = e0[idx];
        uint4 b = e1[idx];
        __half2 q0 = __hadd2(__hmul2(h2(a.x), h2(u.x)), __hmul2(h2(a.y), h2(u.y)));
        __half2 q1 = __hadd2(__hmul2(h2(a.z), h2(u.z)), __hmul2(h2(a.w), h2(u.w)));
        float2 f0 = __half22float2(q0);
        float2 f1 = __half22float2(q1);
        s0a += f0.x + f0.y;
        s0b += f1.x + f1.y;
        __half2 q2 = __hadd2(__hmul2(h2(b.x), h2(u.x)), __hmul2(h2(b.y), h2(u.y)));
        __half2 q3 = __hadd2(__hmul2(h2(b.z), h2(u.z)), __hmul2(h2(b.w), h2(u.w)));
        float2 f2 = __half22float2(q2);
        float2 f3 = __half22float2(q3);
        s1a += f2.x + f2.y;
        s1b += f3.x + f3.y;
    }
    s0 = s0a + s0b;
    s1 = s1a + s1b;
}

__global__ __launch_bounds__(NTHR, 1)
void sinkhorn_kernel(const float* __restrict__ logits,
                     const float* __restrict__ noise,
                     float* __restrict__ out) {
    extern __shared__ __align__(16) unsigned char smraw[];
    __half* Eh_sm = reinterpret_cast<__half*>(smraw);                    // CROWS x DIM
    __half* u_h   = reinterpret_cast<__half*>(smraw + CROWS * DIM * 2);  // DIM
    float*  tailf = reinterpret_cast<float*>(smraw + CROWS * DIM * 2 + DIM * 2);
    float*  v_sm  = tailf;         // 32 floats
    float*  p_sm  = tailf + 32;    // 32 floats
    float*  v_bc  = tailf + 64;    // 1 float   (all inside the +512 pad)

    const int tid  = threadIdx.x;
    const int bid  = blockIdx.x;
    const int lane = tid & 31;
    const int wid  = tid >> 5;
    const int nr   = (DIM - bid + NBLK - 1) / NBLK;   // 28 (bid<100) else 27
    const int rep  = bid & (NREP - 1);
    unsigned epoch = 0;

    auto gsync = [&]() {
        __syncthreads();
        ++epoch;
        if (tid == 0) {
            bar_arrive_release();
            const unsigned target = epoch * NBLK;
            while (bar_poll_acquire() < target) { }
        }
        __syncthreads();
    };

    // ================= setup: block-cooperative per row =================
    {
        float4 acc = make_float4(0.f, 0.f, 0.f, 0.f);
        float4 l = reinterpret_cast<const float4*>(logits + (size_t)bid * DIM)[tid];
        float4 n = reinterpret_cast<const float4*>(noise  + (size_t)bid * DIM)[tid];
        for (int k = 0; k < nr; ++k) {
            float4 e;
            e.x = gumbel_exp(l.x, n.x);
            e.y = gumbel_exp(l.y, n.y);
            e.z = gumbel_exp(l.z, n.z);
            e.w = gumbel_exp(l.w, n.w);
            if (k + 1 < nr) {   // prefetch next row past the reduction
                const int nrow = (k + 1) * NBLK + bid;
                l = reinterpret_cast<const float4*>(logits + (size_t)nrow * DIM)[tid];
                n = reinterpret_cast<const float4*>(noise  + (size_t)nrow * DIM)[tid];
            }
            float s = warp_sum((e.x + e.y) + (e.z + e.w));
            if (lane == 0) p_sm[wid] = s;
            __syncthreads();
            if (wid == 0) {
                float t = warp_sum(p_sm[lane]);
                if (lane == 0) *v_bc = __frcp_rn(t);
            }
            __syncthreads();
            const float vin = *v_bc;
            __half2 h0 = __floats2half2_rn(e.x * vin, e.y * vin);
            __half2 h1 = __floats2half2_rn(e.z * vin, e.w * vin);
            uint2 r;
            r.x = *reinterpret_cast<unsigned*>(&h0);
            r.y = *reinterpret_cast<unsigned*>(&h1);
            if (k < CROWS)
                reinterpret_cast<uint2*>(Eh_sm + (size_t)k * DIM)[tid] = r;
            else
                reinterpret_cast<uint2*>(g_Eh + (size_t)(k * NBLK + bid) * DIM)[tid] = r;
            float4 q = cvt4(r);    // accumulate quantized values (exact colsums)
            acc.x += q.x; acc.y += q.y; acc.z += q.z; acc.w += q.w;
        }
        float* dst = g_usum[0][rep];
        atomicAdd(&dst[4 * tid + 0], acc.x);
        atomicAdd(&dst[4 * tid + 1], acc.y);
        atomicAdd(&dst[4 * tid + 2], acc.z);
        atomicAdd(&dst[4 * tid + 3], acc.w);
    }
    gsync();

    // ================ 19 fused iterations ================
    for (int it = 0; it < NITER - 1; ++it) {
        const int rb = it % 3;
        const int wb = (it + 1) % 3;   // pre-zeroed
        const int zb = (it + 2) % 3;   // zero now for use next iteration

        // u_h = fp16(1 / sum of replicas)   (L2 reads, bypass L1)
        {
            float4 a = __ldcg(reinterpret_cast<const float4*>(g_usum[rb][0]) + tid);
            float4 b = __ldcg(reinterpret_cast<const float4*>(g_usum[rb][1]) + tid);
            float4 c = __ldcg(reinterpret_cast<const float4*>(g_usum[rb][2]) + tid);
            float4 d = __ldcg(reinterpret_cast<const float4*>(g_usum[rb][3]) + tid);
            float sx = (a.x + b.x) + (c.x + d.x);
            float sy = (a.y + b.y) + (c.y + d.y);
            float sz = (a.z + b.z) + (c.z + d.z);
            float sw = (a.w + b.w) + (c.w + d.w);
            __half2 h0 = __floats2half2_rn(__frcp_rn(sx), __frcp_rn(sy));
            __half2 h1 = __floats2half2_rn(__frcp_rn(sz), __frcp_rn(sw));
            uint2 r;
            r.x = *reinterpret_cast<unsigned*>(&h0);
            r.y = *reinterpret_cast<unsigned*>(&h1);
            reinterpret_cast<uint2*>(u_h)[tid] = r;
        }
        if (tid < 111) {   // zero stale replica buffer
            int i = bid * 111 + tid;
            if (i < NREP * DIM) ((float*)g_usum[zb])[i] = 0.0f;
        }
        __syncthreads();

        // ---- row pass: warp w owns rows w (smem for w<CROWS) and w+14 (L1) ----
        if (wid < 14) {
            const int r0 = wid, r1 = wid + 14;
            const bool has1 = (r1 < nr);
            const uint4* u4 = reinterpret_cast<const uint4*>(u_h);
            const uint4* e1 = reinterpret_cast<const uint4*>(
                g_Eh + (size_t)((has1 ? r1 : CROWS) * NBLK + bid) * DIM);
            float s0, s1;
            if (wid < CROWS) {
                const uint4* e0 = reinterpret_cast<const uint4*>(Eh_sm + (size_t)r0 * DIM);
                dot2(e0, e1, u4, lane, s0, s1);
            } else {
                const uint4* e0 = reinterpret_cast<const uint4*>(g_Eh + (size_t)(r0 * NBLK + bid) * DIM);
                dot2(e0, e1, u4, lane, s0, s1);
            }
            s0 = warp_sum(s0);
            s1 = warp_sum(s1);
            if (lane == 0) {
                v_sm[r0] = __frcp_rn(s0);
                if (has1) v_sm[r1] = __frcp_rn(s1);
            }
        }
        __syncthreads();

        // ---- col pass: smem rows + L1 rows, thread-per-4cols ----
        {
            float4 acc = make_float4(0.f, 0.f, 0.f, 0.f);
            #pragma unroll
            for (int k = 0; k < CROWS; ++k) {
                float4 e = cvt4(reinterpret_cast<const uint2*>(Eh_sm + (size_t)k * DIM)[tid]);
                const float vv = v_sm[k];
                acc.x = fmaf(e.x, vv, acc.x);
                acc.y = fmaf(e.y, vv, acc.y);
                acc.z = fmaf(e.z, vv, acc.z);
                acc.w = fmaf(e.w, vv, acc.w);
            }
            #pragma unroll 4
            for (int k = CROWS; k < nr; ++k) {
                float4 e = cvt4(reinterpret_cast<const uint2*>(g_Eh + (size_t)(k * NBLK + bid) * DIM)[tid]);
                const float vv = v_sm[k];
                acc.x = fmaf(e.x, vv, acc.x);
                acc.y = fmaf(e.y, vv, acc.y);
                acc.z = fmaf(e.z, vv, acc.z);
                acc.w = fmaf(e.w, vv, acc.w);
            }
            float* dst = g_usum[wb][rep];
            atomicAdd(&dst[4 * tid + 0], acc.x);
            atomicAdd(&dst[4 * tid + 1], acc.y);
            atomicAdd(&dst[4 * tid + 2], acc.z);
            atomicAdd(&dst[4 * tid + 3], acc.w);
        }
        gsync();
    }

    // ================ final: out = Ê * v * u  (u in fp32) ================
    {
        const int fb = (NITER - 1) % 3;
        float4 a = __ldcg(reinterpret_cast<const float4*>(g_usum[fb][0]) + tid);
        float4 b = __ldcg(reinterpret_cast<const float4*>(g_usum[fb][1]) + tid);
        float4 c = __ldcg(reinterpret_cast<const float4*>(g_usum[fb][2]) + tid);
        float4 d = __ldcg(reinterpret_cast<const float4*>(g_usum[fb][3]) + tid);
        const float ux = __frcp_rn((a.x + b.x) + (c.x + d.x));
        const float uy = __frcp_rn((a.y + b.y) + (c.y + d.y));
        const float uz = __frcp_rn((a.z + b.z) + (c.z + d.z));
        const float uw = __frcp_rn((a.w + b.w) + (c.w + d.w));
        #pragma unroll 4
        for (int k = 0; k < nr; ++k) {
            const int row = k * NBLK + bid;
            float4 e = cvt4((k < CROWS)
                ? reinterpret_cast<const uint2*>(Eh_sm + (size_t)k * DIM)[tid]
                : reinterpret_cast<const uint2*>(g_Eh + (size_t)row * DIM)[tid]);
            const float vv = v_sm[k];
            float4 o;
            o.x = e.x * vv * ux;
            o.y = e.y * vv * uy;
            o.z = e.z * vv * uz;
            o.w = e.w * vv * uw;
            reinterpret_cast<float4*>(out + (size_t)row * DIM)[tid] = o;
        }
    }
}

extern "C" void kernel_launch(void* const* d_in, const int* in_sizes, int n_in,
                              void* d_out, int out_size) {
    const float* logits = (const float*)d_in[0];
    const float* noise  = (const float*)d_in[1];
    float* out = (float*)d_out;

    static bool configured = false;
    if (!configured) {
        cudaFuncSetAttribute(sinkhorn_kernel,
                             cudaFuncAttributeMaxDynamicSharedMemorySize, SMEM_BYTES);
        configured = true;
    }

    reset_kernel<<<48, 1024>>>();
    sinkhorn_kernel<<<NBLK, NTHR, SMEM_BYTES>>>(logits, noise, out);
}